// round 3
// baseline (speedup 1.0000x reference)
#include <cuda_runtime.h>
#include <math.h>

// Problem constants (fixed by the dataset)
#define NB 4
#define NP 256
#define NC 151
#define NR 51
#define WREL 0.5f
#define NL NC                 // label classes index into [0,151)
#define NK (2*NL*NR)          // 15402 combined contraction dim (d,l,r)
#define NZSTRIDE 15404        // padded to multiple of 4 for int4 loads

// Static scratch (no allocations allowed)
__device__ float d_Hw[NB * NK * NP];            // [b][k=(d,l,r)][q]  ~63 MB
__device__ float d_theta[NB * NC * NP];         // [b][c][q]
__device__ int   d_nzk[NC * NZSTRIDE];          // per-c sparse lists over k
__device__ int   d_nzcnt[NC];
__device__ int   d_binStart[NB][NL + 1];
__device__ int   d_perm[NB][NP];
__device__ float d_loss[NB * NP];

// ---------------------------------------------------------------------------
// 1) Per-image label binning (deterministic, stable order)
// ---------------------------------------------------------------------------
__global__ void bin_kernel(const int* __restrict__ labels) {
    int b = blockIdx.x;
    __shared__ int slab[NP];
    __shared__ int scnt[NL];
    __shared__ int soff[NL + 1];
    int t = threadIdx.x;
    if (t < NP) slab[t] = labels[b * NP + t];
    __syncthreads();
    if (t < NL) {
        int c = 0;
        for (int i = 0; i < NP; i++) c += (slab[i] == t);
        scnt[t] = c;
    }
    __syncthreads();
    if (t == 0) {
        int acc = 0;
        for (int l = 0; l < NL; l++) { soff[l] = acc; acc += scnt[l]; }
        soff[NL] = acc;
    }
    __syncthreads();
    if (t <= NL) d_binStart[b][t] = soff[t];
    if (t < NL) {
        int o = soff[t];
        for (int i = 0; i < NP; i++)
            if (slab[i] == t) d_perm[b][o++] = i;
    }
}

// ---------------------------------------------------------------------------
// 2) H build: block per (l, d, b). Sums rel rows (d=0: over first index,
//    d=1: over second index) for points whose label == l, folds w_r,
//    writes Hw[b][d][l][r][q] (q innermost for coalesced consumption).
//    Empty bins naturally write zeros -> no pre-zeroing of Hw needed.
// ---------------------------------------------------------------------------
__global__ void hbuild_kernel(const float* __restrict__ rel) {
    int l = blockIdx.x, d = blockIdx.y, b = blockIdx.z;
    __shared__ float s[64 * 53];   // q-tile 64 x r 51, pad to 53 (odd) vs conflicts
    int start = d_binStart[b][l];
    int end   = d_binStart[b][l + 1];
    float* out = d_Hw + (size_t)(((b * 2 + d) * NL + l) * NR) * NP;

    for (int q0 = 0; q0 < NP; q0 += 64) {
        for (int i = threadIdx.x; i < 64 * 53; i += 256) s[i] = 0.0f;
        __syncthreads();
        for (int m = start; m < end; m++) {
            int p = d_perm[b][m];
            if (d == 0) {
                const float* base = rel + ((size_t)((b * NP + p) * NP + q0)) * NR;
                for (int idx = threadIdx.x; idx < 64 * NR; idx += 256) {
                    int tq = idx / NR, r = idx - tq * NR;
                    s[tq * 53 + r] += base[idx];
                }
            } else {
                for (int idx = threadIdx.x; idx < 64 * NR; idx += 256) {
                    int tq = idx / NR, r = idx - tq * NR;
                    s[tq * 53 + r] += rel[((size_t)((b * NP + q0 + tq) * NP + p)) * NR + r];
                }
            }
            // no sync needed: fixed thread->slot mapping across members
        }
        __syncthreads();
        for (int idx = threadIdx.x; idx < NR * 64; idx += 256) {
            int r = idx / 64, tq = idx - r * 64;
            float w = (r == 0) ? 1.0f : WREL;
            out[r * NP + q0 + tq] = w * s[tq * 53 + r];
        }
        __syncthreads();
    }
}

// ---------------------------------------------------------------------------
// 3) Sparse list build per c (one warp per block, ballot compaction ->
//    ascending-k deterministic order).
//    k = d*NL*NR + l*NR + r ; d=0 tests M[l,c,r], d=1 tests M[c,l,r].
// ---------------------------------------------------------------------------
__global__ void listbuild_kernel(const float* __restrict__ M) {
    int c = blockIdx.x;
    int lane = threadIdx.x;
    int cnt = 0;
    int* list = d_nzk + c * NZSTRIDE;
    for (int base = 0; base < NK; base += 32) {
        int k = base + lane;
        float v = 0.0f;
        if (k < NK) {
            int d = k / (NL * NR);
            int lr = k - d * NL * NR;
            int l = lr / NR, r = lr - l * NR;
            v = (d == 0) ? M[((size_t)l * NC + c) * NR + r]
                         : M[((size_t)c * NC + l) * NR + r];
        }
        unsigned mask = __ballot_sync(0xFFFFFFFFu, v != 0.0f);
        if (v != 0.0f) {
            int pos = cnt + __popc(mask & ((1u << lane) - 1u));
            list[pos] = k;
        }
        cnt += __popc(mask);
    }
    if (lane == 0) d_nzcnt[c] = cnt;
}

// ---------------------------------------------------------------------------
// 4) Sparse accumulate: theta[b][c][q] = 0.5 * sum_{k in nz(c)} Hw[b][k][q]
//    warp = one c, lanes = 32 consecutive q (128B coalesced loads).
// ---------------------------------------------------------------------------
__global__ void accum_kernel() {
    int warp = threadIdx.x >> 5, lane = threadIdx.x & 31;
    int c = blockIdx.x * 8 + warp;
    int q = blockIdx.y * 32 + lane;
    int b = blockIdx.z;
    if (c >= NC) return;
    const float* H = d_Hw + (size_t)b * NK * NP + q;
    const int* list = d_nzk + c * NZSTRIDE;
    int n = d_nzcnt[c];
    float acc = 0.0f;
    int i = 0;
    for (; i + 4 <= n; i += 4) {
        int4 k4 = *(const int4*)(list + i);   // NZSTRIDE keeps 16B alignment
        acc += H[(size_t)k4.x * NP];
        acc += H[(size_t)k4.y * NP];
        acc += H[(size_t)k4.z * NP];
        acc += H[(size_t)k4.w * NP];
    }
    for (; i < n; i++) acc += H[(size_t)list[i] * NP];
    d_theta[((size_t)b * NC + c) * NP + q] = 0.5f * acc;
}

// ---------------------------------------------------------------------------
// 5) Loss: per (b,q) block. Diagonal correction + log-softmax over c,
//    pick c = lab[q]. Fixed-tree reductions (deterministic).
// ---------------------------------------------------------------------------
__global__ void loss_kernel(const float* __restrict__ rel,
                            const float* __restrict__ M,
                            const int* __restrict__ labels) {
    int q = blockIdx.x, b = blockIdx.y;
    int c = threadIdx.x;
    __shared__ float srel[NR];
    __shared__ int slab;
    __shared__ float red[256];
    if (threadIdx.x == 0) slab = labels[b * NP + q];
    if (threadIdx.x < NR)
        srel[threadIdx.x] = rel[((size_t)(b * NP + q) * NP + q) * NR + threadIdx.x];
    __syncthreads();
    int lab = slab;
    float t = -INFINITY;
    if (c < NC) {
        const float* Ma = M + ((size_t)lab * NC + c) * NR;
        const float* Mb = M + ((size_t)c * NC + lab) * NR;
        float D = 0.0f;
        #pragma unroll 1
        for (int r = 0; r < NR; r++) {
            float w = (r == 0) ? 1.0f : WREL;
            D += w * srel[r] * (Ma[r] + Mb[r]);
        }
        t = d_theta[((size_t)b * NC + c) * NP + q] - 0.5f * D;
    }
    red[threadIdx.x] = t;
    __syncthreads();
    for (int s = 128; s > 0; s >>= 1) {
        if (threadIdx.x < s) red[threadIdx.x] = fmaxf(red[threadIdx.x], red[threadIdx.x + s]);
        __syncthreads();
    }
    float mx = red[0];
    __syncthreads();
    float e = (c < NC) ? expf(t - mx) : 0.0f;
    red[threadIdx.x] = e;
    __syncthreads();
    for (int s = 128; s > 0; s >>= 1) {
        if (threadIdx.x < s) red[threadIdx.x] += red[threadIdx.x + s];
        __syncthreads();
    }
    float lse = mx + logf(red[0]);
    if (c == lab) d_loss[b * NP + q] = lse - t;
}

// ---------------------------------------------------------------------------
// 6) Mean over 1024 losses -> scalar output (fixed-order reduction)
// ---------------------------------------------------------------------------
__global__ void mean_kernel(float* __restrict__ out) {
    __shared__ float red[256];
    int t = threadIdx.x;
    float v = d_loss[t] + d_loss[t + 256] + d_loss[t + 512] + d_loss[t + 768];
    red[t] = v;
    __syncthreads();
    for (int s = 128; s > 0; s >>= 1) {
        if (t < s) red[t] += red[t + s];
        __syncthreads();
    }
    if (t == 0) out[0] = red[0] * (1.0f / (NB * NP));
}

// ---------------------------------------------------------------------------
extern "C" void kernel_launch(void* const* d_in, const int* in_sizes, int n_in,
                              void* d_out, int out_size) {
    // inputs: 0=roi_scores (unused: _unary is dead code in the reference),
    //         1=rel_scores, 2=relationship_mat, 3=roi_labels, 4=num_images
    const float* rel    = (const float*)d_in[1];
    const float* M      = (const float*)d_in[2];
    const int*   labels = (const int*)d_in[3];
    float* out = (float*)d_out;

    bin_kernel<<<NB, 256>>>(labels);
    listbuild_kernel<<<NC, 32>>>(M);
    hbuild_kernel<<<dim3(NL, 2, NB), 256>>>(rel);
    accum_kernel<<<dim3((NC + 7) / 8, NP / 32, NB), 256>>>();
    loss_kernel<<<dim3(NP, NB), 256>>>(rel, M, labels);
    mean_kernel<<<1, 256>>>(out);
}

// round 4
// speedup vs baseline: 1.1659x; 1.1659x over previous
#include <cuda_runtime.h>
#include <math.h>

// Problem constants (fixed by the dataset)
#define NB 4
#define NP 256
#define NC 151
#define NR 51
#define WREL 0.5f
#define NL NC                 // label classes index into [0,151)
#define NK (2*NL*NR)          // 15402 combined contraction dim (d,l,r)
#define NZSTRIDE 15408        // padded to multiple of 8 for unrolled int4 loads

// Static scratch (no allocations allowed)
__device__ float d_Hw[NB * NK * NP];            // [b][k=(d,l,r)][q]  ~63 MB
__device__ float d_theta[NB * NC * NP];         // [b][c][q]
__device__ int   d_nzk[NC * NZSTRIDE];          // per-c sparse lists over k
__device__ int   d_nzcnt[NC];
__device__ int   d_binStart[NB][NL + 1];
__device__ int   d_perm[NB][NP];
__device__ float d_loss[NB * NP];

// ---------------------------------------------------------------------------
// 1) Per-image label binning (deterministic, stable order)
// ---------------------------------------------------------------------------
__global__ void bin_kernel(const int* __restrict__ labels) {
    int b = blockIdx.x;
    __shared__ int slab[NP];
    __shared__ int scnt[NL];
    __shared__ int soff[NL + 1];
    int t = threadIdx.x;
    if (t < NP) slab[t] = labels[b * NP + t];
    __syncthreads();
    if (t < NL) {
        int c = 0;
        for (int i = 0; i < NP; i++) c += (slab[i] == t);
        scnt[t] = c;
    }
    __syncthreads();
    if (t == 0) {
        int acc = 0;
        for (int l = 0; l < NL; l++) { soff[l] = acc; acc += scnt[l]; }
        soff[NL] = acc;
    }
    __syncthreads();
    if (t <= NL) d_binStart[b][t] = soff[t];
    if (t < NL) {
        int o = soff[t];
        for (int i = 0; i < NP; i++)
            if (slab[i] == t) d_perm[b][o++] = i;
    }
}

// ---------------------------------------------------------------------------
// 2) H build, register-accumulated.
//    Block per (l, q-tile(64), d, b). Each thread owns NEL=13 fixed (tq,r)
//    slots in registers; member loop issues 13 independent LDG+FADD per
//    member (high MLP, no smem dependency chain). One smem pass at the end
//    transposes (tq,r) -> (r,q-major) and folds w_r.
//    Empty bins naturally write zeros -> no pre-zeroing of Hw needed.
// ---------------------------------------------------------------------------
#define TILEQ 64
#define TILE_ELEMS (TILEQ * NR)          // 3264
#define NEL 13                           // ceil(3264/256)

__global__ void hbuild_kernel(const float* __restrict__ rel) {
    int bx = blockIdx.x;
    int l = bx >> 2;
    int q0 = (bx & 3) * TILEQ;
    int d = blockIdx.y, b = blockIdx.z;
    int t = threadIdx.x;

    __shared__ float s[TILEQ * 53];      // pad 53 (odd) -> conflict-free transpose

    int start = d_binStart[b][l];
    int end   = d_binStart[b][l + 1];

    float reg[NEL];
    #pragma unroll
    for (int j = 0; j < NEL; j++) reg[j] = 0.0f;

    if (d == 0) {
        // out[tq][r] = sum_m rel[b, p_m, q0+tq, r] : contiguous 3264-elem slab per m
        for (int m = start; m < end; m++) {
            int p = d_perm[b][m];
            const float* base = rel + ((size_t)((b * NP + p) * NP + q0)) * NR;
            #pragma unroll
            for (int j = 0; j < NEL; j++) {
                int idx = t + j * 256;
                if (idx < TILE_ELEMS) reg[j] += __ldg(base + idx);
            }
        }
    } else {
        // out[tq][r] = sum_m rel[b, q0+tq, p_m, r] : per-slot base + p*NR
        const float* base[NEL];
        #pragma unroll
        for (int j = 0; j < NEL; j++) {
            int idx = t + j * 256;
            int tq = idx / NR, r = idx - tq * NR;
            base[j] = rel + ((size_t)(b * NP + q0 + tq) * NP) * NR + r;
        }
        for (int m = start; m < end; m++) {
            int p = d_perm[b][m];
            size_t off = (size_t)p * NR;
            #pragma unroll
            for (int j = 0; j < NEL; j++) {
                int idx = t + j * 256;
                if (idx < TILE_ELEMS) reg[j] += __ldg(base[j] + off);
            }
        }
    }

    // Stage to smem in (tq, r) order
    #pragma unroll
    for (int j = 0; j < NEL; j++) {
        int idx = t + j * 256;
        if (idx < TILE_ELEMS) {
            int tq = idx / NR, r = idx - tq * NR;
            s[tq * 53 + r] = reg[j];
        }
    }
    __syncthreads();

    // Write transposed: Hw[b][d][l][r][q0+tq], fold w_r. Coalesced 64-f stores.
    float* out = d_Hw + (size_t)(((b * 2 + d) * NL + l) * NR) * NP + q0;
    for (int idx = t; idx < NR * TILEQ; idx += 256) {
        int r = idx >> 6, tq = idx & 63;
        float w = (r == 0) ? 1.0f : WREL;
        out[r * NP + tq] = w * s[tq * 53 + r];
    }
}

// ---------------------------------------------------------------------------
// 3) Sparse list build per c (one warp per block, ballot compaction ->
//    ascending-k deterministic order).
//    k = d*NL*NR + l*NR + r ; d=0 tests M[l,c,r], d=1 tests M[c,l,r].
// ---------------------------------------------------------------------------
__global__ void listbuild_kernel(const float* __restrict__ M) {
    int c = blockIdx.x;
    int lane = threadIdx.x;
    int cnt = 0;
    int* list = d_nzk + c * NZSTRIDE;
    for (int base = 0; base < NK; base += 32) {
        int k = base + lane;
        float v = 0.0f;
        if (k < NK) {
            int d = k / (NL * NR);
            int lr = k - d * NL * NR;
            int l = lr / NR, r = lr - l * NR;
            v = (d == 0) ? M[((size_t)l * NC + c) * NR + r]
                         : M[((size_t)c * NC + l) * NR + r];
        }
        unsigned mask = __ballot_sync(0xFFFFFFFFu, v != 0.0f);
        if (v != 0.0f) {
            int pos = cnt + __popc(mask & ((1u << lane) - 1u));
            list[pos] = k;
        }
        cnt += __popc(mask);
    }
    if (lane == 0) d_nzcnt[c] = cnt;
}

// ---------------------------------------------------------------------------
// 4) Sparse accumulate: theta[b][c][q] = 0.5 * sum_{k in nz(c)} Hw[b][k][q]
//    warp = one c, lane = one float2 (2 consecutive q) -> 256B/warp/row.
//    8-deep k unroll with 4 accumulator pairs for MLP=8.
// ---------------------------------------------------------------------------
__global__ void accum_kernel() {
    int warp = threadIdx.x >> 5, lane = threadIdx.x & 31;
    int c = blockIdx.x * 8 + warp;
    int q2 = blockIdx.y * 32 + lane;          // float2 index; q = 2*q2
    int b = blockIdx.z;
    if (c >= NC) return;
    const float2* H = (const float2*)(d_Hw + (size_t)b * NK * NP) + q2;
    const int* list = d_nzk + c * NZSTRIDE;
    int n = d_nzcnt[c];
    float2 a0 = make_float2(0.f, 0.f), a1 = a0, a2 = a0, a3 = a0;
    int i = 0;
    for (; i + 8 <= n; i += 8) {
        int4 ka = *(const int4*)(list + i);
        int4 kb = *(const int4*)(list + i + 4);
        float2 v0 = H[(size_t)ka.x * (NP / 2)];
        float2 v1 = H[(size_t)ka.y * (NP / 2)];
        float2 v2 = H[(size_t)ka.z * (NP / 2)];
        float2 v3 = H[(size_t)ka.w * (NP / 2)];
        float2 v4 = H[(size_t)kb.x * (NP / 2)];
        float2 v5 = H[(size_t)kb.y * (NP / 2)];
        float2 v6 = H[(size_t)kb.z * (NP / 2)];
        float2 v7 = H[(size_t)kb.w * (NP / 2)];
        a0.x += v0.x; a0.y += v0.y; a1.x += v1.x; a1.y += v1.y;
        a2.x += v2.x; a2.y += v2.y; a3.x += v3.x; a3.y += v3.y;
        a0.x += v4.x; a0.y += v4.y; a1.x += v5.x; a1.y += v5.y;
        a2.x += v6.x; a2.y += v6.y; a3.x += v7.x; a3.y += v7.y;
    }
    for (; i < n; i++) {
        float2 v = H[(size_t)list[i] * (NP / 2)];
        a0.x += v.x; a0.y += v.y;
    }
    float2 r;
    r.x = 0.5f * (a0.x + a1.x + a2.x + a3.x);
    r.y = 0.5f * (a0.y + a1.y + a2.y + a3.y);
    float2* T = (float2*)(d_theta + ((size_t)b * NC + c) * NP) + q2;
    *T = r;
}

// ---------------------------------------------------------------------------
// 5) Loss: per (b,q) block. Diagonal correction + log-softmax over c,
//    pick c = lab[q]. Fixed-tree reductions (deterministic).
// ---------------------------------------------------------------------------
__global__ void loss_kernel(const float* __restrict__ rel,
                            const float* __restrict__ M,
                            const int* __restrict__ labels) {
    int q = blockIdx.x, b = blockIdx.y;
    int c = threadIdx.x;
    __shared__ float srel[NR];
    __shared__ int slab;
    __shared__ float red[256];
    if (threadIdx.x == 0) slab = labels[b * NP + q];
    if (threadIdx.x < NR)
        srel[threadIdx.x] = rel[((size_t)(b * NP + q) * NP + q) * NR + threadIdx.x];
    __syncthreads();
    int lab = slab;
    float t = -INFINITY;
    if (c < NC) {
        const float* Ma = M + ((size_t)lab * NC + c) * NR;
        const float* Mb = M + ((size_t)c * NC + lab) * NR;
        float D = 0.0f;
        #pragma unroll 1
        for (int r = 0; r < NR; r++) {
            float w = (r == 0) ? 1.0f : WREL;
            D += w * srel[r] * (Ma[r] + Mb[r]);
        }
        t = d_theta[((size_t)b * NC + c) * NP + q] - 0.5f * D;
    }
    red[threadIdx.x] = t;
    __syncthreads();
    for (int s = 128; s > 0; s >>= 1) {
        if (threadIdx.x < s) red[threadIdx.x] = fmaxf(red[threadIdx.x], red[threadIdx.x + s]);
        __syncthreads();
    }
    float mx = red[0];
    __syncthreads();
    float e = (c < NC) ? expf(t - mx) : 0.0f;
    red[threadIdx.x] = e;
    __syncthreads();
    for (int s = 128; s > 0; s >>= 1) {
        if (threadIdx.x < s) red[threadIdx.x] += red[threadIdx.x + s];
        __syncthreads();
    }
    float lse = mx + logf(red[0]);
    if (c == lab) d_loss[b * NP + q] = lse - t;
}

// ---------------------------------------------------------------------------
// 6) Mean over 1024 losses -> scalar output (fixed-order reduction)
// ---------------------------------------------------------------------------
__global__ void mean_kernel(float* __restrict__ out) {
    __shared__ float red[256];
    int t = threadIdx.x;
    float v = d_loss[t] + d_loss[t + 256] + d_loss[t + 512] + d_loss[t + 768];
    red[t] = v;
    __syncthreads();
    for (int s = 128; s > 0; s >>= 1) {
        if (t < s) red[t] += red[t + s];
        __syncthreads();
    }
    if (t == 0) out[0] = red[0] * (1.0f / (NB * NP));
}

// ---------------------------------------------------------------------------
extern "C" void kernel_launch(void* const* d_in, const int* in_sizes, int n_in,
                              void* d_out, int out_size) {
    // inputs: 0=roi_scores (unused: _unary is dead code in the reference),
    //         1=rel_scores, 2=relationship_mat, 3=roi_labels, 4=num_images
    const float* rel    = (const float*)d_in[1];
    const float* M      = (const float*)d_in[2];
    const int*   labels = (const int*)d_in[3];
    float* out = (float*)d_out;

    bin_kernel<<<NB, 256>>>(labels);
    listbuild_kernel<<<NC, 32>>>(M);
    hbuild_kernel<<<dim3(NL * 4, 2, NB), 256>>>(rel);
    accum_kernel<<<dim3((NC + 7) / 8, NP / 64, NB), 256>>>();
    loss_kernel<<<dim3(NP, NB), 256>>>(rel, M, labels);
    mean_kernel<<<1, 256>>>(out);
}

// round 9
// speedup vs baseline: 1.4447x; 1.2391x over previous
#include <cuda_runtime.h>
#include <math.h>

// Problem constants (fixed by the dataset)
#define NB 4
#define NP 256
#define NC 151
#define NR 51
#define WREL 0.5f
#define NL NC                 // label classes index into [0,151)
#define NK (2*NL*NR)          // 15402 combined contraction dim (d,l,r)
#define NZSTRIDE 15408        // padded to multiple of 8 for unrolled int4 loads
#define NS 8                  // split-k factor in accum

// Static scratch (no allocations allowed)
__device__ float d_Hw[NB * NK * NP];            // [b][k=(d,l,r)][q], ALL rows pre-scaled by WREL
__device__ float d_thetaPart[NS * NB * NC * NP];// split-k partials [s][b][c][q]
__device__ float d_dense0[NB * NP];             // sum of r=0 plane (W-scaled)
__device__ int   d_nzk[NC * NZSTRIDE];          // per-c sparse lists over k (r>=1 only)
__device__ int   d_nzcnt[NC];
__device__ int   d_binStart[NB][NL + 1];
__device__ int   d_perm[NB][NP];
__device__ float d_loss[NB * NP];

// ---------------------------------------------------------------------------
// 1) Per-image label binning (deterministic, stable order)
// ---------------------------------------------------------------------------
__global__ void bin_kernel(const int* __restrict__ labels) {
    int b = blockIdx.x;
    __shared__ int slab[NP];
    __shared__ int scnt[NL];
    __shared__ int soff[NL + 1];
    int t = threadIdx.x;
    if (t < NP) slab[t] = labels[b * NP + t];
    __syncthreads();
    if (t < NL) {
        int c = 0;
        #pragma unroll 8
        for (int i = 0; i < NP; i++) c += (slab[i] == t);
        scnt[t] = c;
    }
    __syncthreads();
    if (t == 0) {
        int acc = 0;
        for (int l = 0; l < NL; l++) { soff[l] = acc; acc += scnt[l]; }
        soff[NL] = acc;
    }
    __syncthreads();
    if (t <= NL) d_binStart[b][t] = soff[t];
    if (t < NL) {
        int o = soff[t];
        for (int i = 0; i < NP; i++)
            if (slab[i] == t) d_perm[b][o++] = i;
    }
}

// ---------------------------------------------------------------------------
// 2) H build, register-accumulated. Block per (l, q-tile(64), d, b).
//    Each thread owns NEL=13 fixed (tq,r) slots in registers (int offsets,
//    not pointers, to keep register count low). All rows scaled by WREL
//    (r=0 rows are only consumed by dense0, which compensates).
// ---------------------------------------------------------------------------
#define TILEQ 64
#define TILE_ELEMS (TILEQ * NR)          // 3264
#define NEL 13                           // ceil(3264/256)

__global__ void hbuild_kernel(const float* __restrict__ rel) {
    int bx = blockIdx.x;
    int l = bx >> 2;
    int q0 = (bx & 3) * TILEQ;
    int d = blockIdx.y, b = blockIdx.z;
    int t = threadIdx.x;

    __shared__ float s[TILEQ * 53];      // pad 53 (odd) -> conflict-free transpose

    int start = d_binStart[b][l];
    int end   = d_binStart[b][l + 1];

    float reg[NEL];
    #pragma unroll
    for (int j = 0; j < NEL; j++) reg[j] = 0.0f;

    if (d == 0) {
        // out[tq][r] = sum_m rel[b, p_m, q0+tq, r] : contiguous 3264-elem slab per m
        const float* relb = rel + (size_t)b * NP * NP * NR + q0 * NR;
        for (int m = start; m < end; m++) {
            int p = d_perm[b][m];
            const float* base = relb + p * (NP * NR);
            #pragma unroll
            for (int j = 0; j < NEL; j++) {
                int idx = t + j * 256;
                if (idx < TILE_ELEMS) reg[j] += __ldg(base + idx);
            }
        }
    } else {
        // out[tq][r] = sum_m rel[b, q0+tq, p_m, r] : int offsets from one base
        int off[NEL];
        #pragma unroll
        for (int j = 0; j < NEL; j++) {
            int idx = t + j * 256;
            int tq = idx / NR, r = idx - tq * NR;
            off[j] = tq * (NP * NR) + r;
        }
        const float* relb = rel + (size_t)(b * NP + q0) * NP * NR;
        for (int m = start; m < end; m++) {
            int po = d_perm[b][m] * NR;
            #pragma unroll
            for (int j = 0; j < NEL; j++) {
                int idx = t + j * 256;
                if (idx < TILE_ELEMS) reg[j] += __ldg(relb + off[j] + po);
            }
        }
    }

    // Stage to smem in (tq, r) order
    #pragma unroll
    for (int j = 0; j < NEL; j++) {
        int idx = t + j * 256;
        if (idx < TILE_ELEMS) {
            int tq = idx / NR, r = idx - tq * NR;
            s[tq * 53 + r] = reg[j];
        }
    }
    __syncthreads();

    // Write transposed: Hw[b][d][l][r][q0+tq], uniform WREL scale.
    float* out = d_Hw + (size_t)(((b * 2 + d) * NL + l) * NR) * NP + q0;
    for (int idx = t; idx < NR * TILEQ; idx += 256) {
        int r = idx >> 6, tq = idx & 63;
        out[r * NP + tq] = WREL * s[tq * 53 + r];
    }
}

// ---------------------------------------------------------------------------
// 2b) dense0[b][q] = sum over the 302 r=0 rows of Hw (the all-ones M plane,
//     identical contribution for every c). Already WREL-scaled; the loss
//     fold uses t = dense0 + 0.5*part (0.5 * (1/W) * W = ... works out).
// ---------------------------------------------------------------------------
__global__ void dense0_kernel() {
    int b = blockIdx.x, q = threadIdx.x;
    const float* base = d_Hw + (size_t)b * NK * NP + q;
    float acc = 0.0f;
    #pragma unroll 8
    for (int dl = 0; dl < 2 * NL; dl++)
        acc += __ldg(base + (size_t)dl * (NR * NP));
    d_dense0[b * NP + q] = acc;
}

// ---------------------------------------------------------------------------
// 3) Sparse list build per c, r>=1 only (r=0 hoisted into dense0).
//    Ballot compaction -> ascending-k deterministic order.
// ---------------------------------------------------------------------------
__global__ void listbuild_kernel(const float* __restrict__ M) {
    int c = blockIdx.x;
    int lane = threadIdx.x;
    int cnt = 0;
    int* list = d_nzk + c * NZSTRIDE;
    for (int base = 0; base < NK; base += 32) {
        int k = base + lane;
        float v = 0.0f;
        if (k < NK) {
            int d = k / (NL * NR);
            int lr = k - d * NL * NR;
            int l = lr / NR, r = lr - l * NR;
            if (r != 0)
                v = (d == 0) ? M[((size_t)l * NC + c) * NR + r]
                             : M[((size_t)c * NC + l) * NR + r];
        }
        unsigned mask = __ballot_sync(0xFFFFFFFFu, v != 0.0f);
        if (v != 0.0f) {
            int pos = cnt + __popc(mask & ((1u << lane) - 1u));
            list[pos] = k;
        }
        cnt += __popc(mask);
    }
    if (lane == 0) d_nzcnt[c] = cnt;
}

// ---------------------------------------------------------------------------
// 4) Sparse accumulate, split-k: part[s][b][c][q] = sum over k-chunk s of
//    Hw[b][k][q]. warp = one c, lane = one float4 (4 consecutive q).
//    Chunk boundaries rounded to multiples of 4 -> int4 list loads stay
//    aligned. 8-deep unroll, 4 accumulators.
// ---------------------------------------------------------------------------
__global__ void accum_kernel() {
    int warp = threadIdx.x >> 5, lane = threadIdx.x & 31;
    int c = blockIdx.x * 8 + warp;
    int q4 = blockIdx.y * 32 + lane;          // float4 index; q = 4*q4
    int bs = blockIdx.z;
    int b = bs & 3, s = bs >> 2;
    if (c >= NC) return;
    const float4* H = (const float4*)(d_Hw + (size_t)b * NK * NP) + q4;
    const int* list = d_nzk + c * NZSTRIDE;
    int n = d_nzcnt[c];
    int i0 = ((n * s / NS) >> 2) << 2;
    int i1 = (s == NS - 1) ? n : ((n * (s + 1) / NS) >> 2) << 2;
    float4 a0 = make_float4(0.f, 0.f, 0.f, 0.f), a1 = a0, a2 = a0, a3 = a0;
    int i = i0;
    for (; i + 8 <= i1; i += 8) {
        int4 ka = *(const int4*)(list + i);
        int4 kb = *(const int4*)(list + i + 4);
        float4 v0 = __ldg(H + ka.x * (NP / 4));
        float4 v1 = __ldg(H + ka.y * (NP / 4));
        float4 v2 = __ldg(H + ka.z * (NP / 4));
        float4 v3 = __ldg(H + ka.w * (NP / 4));
        float4 v4 = __ldg(H + kb.x * (NP / 4));
        float4 v5 = __ldg(H + kb.y * (NP / 4));
        float4 v6 = __ldg(H + kb.z * (NP / 4));
        float4 v7 = __ldg(H + kb.w * (NP / 4));
        a0.x += v0.x; a0.y += v0.y; a0.z += v0.z; a0.w += v0.w;
        a1.x += v1.x; a1.y += v1.y; a1.z += v1.z; a1.w += v1.w;
        a2.x += v2.x; a2.y += v2.y; a2.z += v2.z; a2.w += v2.w;
        a3.x += v3.x; a3.y += v3.y; a3.z += v3.z; a3.w += v3.w;
        a0.x += v4.x; a0.y += v4.y; a0.z += v4.z; a0.w += v4.w;
        a1.x += v5.x; a1.y += v5.y; a1.z += v5.z; a1.w += v5.w;
        a2.x += v6.x; a2.y += v6.y; a2.z += v6.z; a2.w += v6.w;
        a3.x += v7.x; a3.y += v7.y; a3.z += v7.z; a3.w += v7.w;
    }
    for (; i < i1; i++) {
        float4 v = __ldg(H + list[i] * (NP / 4));
        a0.x += v.x; a0.y += v.y; a0.z += v.z; a0.w += v.w;
    }
    float4 r;
    r.x = a0.x + a1.x + a2.x + a3.x;
    r.y = a0.y + a1.y + a2.y + a3.y;
    r.z = a0.z + a1.z + a2.z + a3.z;
    r.w = a0.w + a1.w + a2.w + a3.w;
    float4* T = (float4*)(d_thetaPart + ((size_t)(s * NB + b) * NC + c) * NP) + q4;
    *T = r;
}

// ---------------------------------------------------------------------------
// 5) Loss: per (b,q) block. Combines split-k partials (fixed s order),
//    dense0 plane, diagonal correction, log-softmax over c.
//    theta = dense0 + 0.5*sum_parts - 0.5*D
// ---------------------------------------------------------------------------
__global__ void loss_kernel(const float* __restrict__ rel,
                            const float* __restrict__ M,
                            const int* __restrict__ labels) {
    int q = blockIdx.x, b = blockIdx.y;
    int c = threadIdx.x;
    __shared__ float sw[NR];             // w_r * rel_diag[r]
    __shared__ int slab;
    __shared__ float red[256];
    if (threadIdx.x == 0) slab = labels[b * NP + q];
    if (threadIdx.x < NR) {
        float v = rel[((size_t)(b * NP + q) * NP + q) * NR + threadIdx.x];
        sw[threadIdx.x] = (threadIdx.x == 0) ? v : WREL * v;
    }
    __syncthreads();
    int lab = slab;
    float t = -INFINITY;
    if (c < NC) {
        const float* Ma = M + ((size_t)lab * NC + c) * NR;
        const float* Mb = M + ((size_t)c * NC + lab) * NR;
        float D = 0.0f;
        #pragma unroll
        for (int r = 0; r < NR; r++)
            D += sw[r] * (__ldg(Ma + r) + __ldg(Mb + r));
        float part = 0.0f;
        #pragma unroll
        for (int s = 0; s < NS; s++)
            part += d_thetaPart[((size_t)(s * NB + b) * NC + c) * NP + q];
        t = d_dense0[b * NP + q] + 0.5f * part - 0.5f * D;
    }
    red[threadIdx.x] = t;
    __syncthreads();
    for (int s = 128; s > 0; s >>= 1) {
        if (threadIdx.x < s) red[threadIdx.x] = fmaxf(red[threadIdx.x], red[threadIdx.x + s]);
        __syncthreads();
    }
    float mx = red[0];
    __syncthreads();
    float e = (c < NC) ? expf(t - mx) : 0.0f;
    red[threadIdx.x] = e;
    __syncthreads();
    for (int s = 128; s > 0; s >>= 1) {
        if (threadIdx.x < s) red[threadIdx.x] += red[threadIdx.x + s];
        __syncthreads();
    }
    float lse = mx + logf(red[0]);
    if (c == lab) d_loss[b * NP + q] = lse - t;
}

// ---------------------------------------------------------------------------
// 6) Mean over 1024 losses -> scalar output (fixed-order reduction)
// ---------------------------------------------------------------------------
__global__ void mean_kernel(float* __restrict__ out) {
    __shared__ float red[256];
    int t = threadIdx.x;
    float v = d_loss[t] + d_loss[t + 256] + d_loss[t + 512] + d_loss[t + 768];
    red[t] = v;
    __syncthreads();
    for (int s = 128; s > 0; s >>= 1) {
        if (t < s) red[t] += red[t + s];
        __syncthreads();
    }
    if (t == 0) out[0] = red[0] * (1.0f / (NB * NP));
}

// ---------------------------------------------------------------------------
extern "C" void kernel_launch(void* const* d_in, const int* in_sizes, int n_in,
                              void* d_out, int out_size) {
    // inputs: 0=roi_scores (unused: _unary is dead code in the reference),
    //         1=rel_scores, 2=relationship_mat, 3=roi_labels, 4=num_images
    const float* rel    = (const float*)d_in[1];
    const float* M      = (const float*)d_in[2];
    const int*   labels = (const int*)d_in[3];
    float* out = (float*)d_out;

    bin_kernel<<<NB, 256>>>(labels);
    listbuild_kernel<<<NC, 32>>>(M);
    hbuild_kernel<<<dim3(NL * 4, 2, NB), 256>>>(rel);
    dense0_kernel<<<NB, NP>>>();
    accum_kernel<<<dim3((NC + 7) / 8, NP / 128, NB * NS), 256>>>();
    loss_kernel<<<dim3(NP, NB), 256>>>(rel, M, labels);
    mean_kernel<<<1, 256>>>(out);
}